// round 13
// baseline (speedup 1.0000x reference)
#include <cuda_runtime.h>
#include <cuda_bf16.h>
#include <math.h>
#include <stdint.h>

// Problem constants (fixed shapes for this benchmark)
#define BSZ 2
#define LSEQ 2048
#define DMODEL 512
#define NHEAD 8
#define EDIM 64
#define NTOK 64
#define NVAR 32

// ---------------- scratch (device globals; no allocation allowed) ----------
__device__ float g_V[BSZ * NHEAD * LSEQ * EDIM];     // fp32 V
__device__ float g_part[BSZ * NHEAD * 32 * 64 * 64]; // partial accumulators
__device__ float g_ml[BSZ * NHEAD * 32 * 64 * 2];    // (m, l) per partial row

// bf16 hi/lo buffers
__device__ __nv_bfloat16 g_xh[4096 * 512], g_xl[4096 * 512];
__device__ __nv_bfloat16 g_wh[3 * 512 * 512], g_wl[3 * 512 * 512];
__device__ __nv_bfloat16 g_Qh[BSZ * NHEAD * LSEQ * EDIM], g_Ql[BSZ * NHEAD * LSEQ * EDIM];
__device__ __nv_bfloat16 g_Kh[BSZ * NHEAD * LSEQ * EDIM], g_Kl[BSZ * NHEAD * LSEQ * EDIM];
__device__ __nv_bfloat16 g_voh[4096 * 512], g_vol[4096 * 512];
__device__ __nv_bfloat16 g_woh[512 * 512], g_wol[512 * 512];

__device__ __forceinline__ uint32_t smem_u32(const void* p) {
    uint32_t a;
    asm("{ .reg .u64 t; cvta.to.shared.u64 t, %1; cvt.u32.u64 %0, t; }"
        : "=r"(a) : "l"(p));
    return a;
}

#define SWZ128(o) ((o) ^ (((o) >> 3) & 0x70))

__device__ __forceinline__ uint32_t pack_hi2(float x, float y) {
    __nv_bfloat16 h0 = __float2bfloat16(x), h1 = __float2bfloat16(y);
    return (uint32_t)__bfloat16_as_ushort(h0) | ((uint32_t)__bfloat16_as_ushort(h1) << 16);
}
__device__ __forceinline__ uint32_t pack_lo2(float x, float y) {
    __nv_bfloat16 h0 = __float2bfloat16(x), h1 = __float2bfloat16(y);
    __nv_bfloat16 l0 = __float2bfloat16(x - __bfloat162float(h0));
    __nv_bfloat16 l1 = __float2bfloat16(y - __bfloat162float(h1));
    return (uint32_t)__bfloat16_as_ushort(l0) | ((uint32_t)__bfloat16_as_ushort(l1) << 16);
}

// ---------------- batched fp32 -> bf16 hi/lo conversion ---------------------
__global__ __launch_bounds__(256) void conv_batch(
    const float* __restrict__ x,
    const float* __restrict__ Wq, const float* __restrict__ Wk,
    const float* __restrict__ Wv, const float* __restrict__ Wo)
{
    int b = blockIdx.x;
    const float* src; __nv_bfloat16 *hi, *lo; int i;
    if (b < 2048) {
        src = x; hi = g_xh; lo = g_xl; i = b * 256 + threadIdx.x;
    } else {
        int seg = (b - 2048) >> 8;
        int sub = (b - 2048) & 255;
        i = sub * 256 + threadIdx.x;
        if (seg == 0)      { src = Wq; hi = g_wh;              lo = g_wl; }
        else if (seg == 1) { src = Wk; hi = g_wh + 262144;     lo = g_wl + 262144; }
        else if (seg == 2) { src = Wv; hi = g_wh + 524288;     lo = g_wl + 524288; }
        else               { src = Wo; hi = g_woh;             lo = g_wol; }
    }
    float4 v = ((const float4*)src)[i];
    uint2 hp, lp;
    hp.x = pack_hi2(v.x, v.y); hp.y = pack_hi2(v.z, v.w);
    lp.x = pack_lo2(v.x, v.y); lp.y = pack_lo2(v.z, v.w);
    ((uint2*)hi)[i] = hp;
    ((uint2*)lo)[i] = lp;
}

// ============ bf16 hi/lo split GEMM: 512-thr, 2-stage cp.async ==============
__device__ __forceinline__ void cpasync16(uint32_t dst, const void* src) {
    asm volatile("cp.async.cg.shared.global [%0], [%1], 16;" :: "r"(dst), "l"(src));
}
__device__ __forceinline__ void ldm_x4(uint32_t r[4], uint32_t addr)
{
    asm volatile("ldmatrix.sync.aligned.m8n8.x4.shared.b16 {%0,%1,%2,%3}, [%4];"
                 : "=r"(r[0]), "=r"(r[1]), "=r"(r[2]), "=r"(r[3]) : "r"(addr));
}
__device__ __forceinline__ void mma_16816(
    float c[4], const uint32_t a[4], uint32_t b0, uint32_t b1)
{
    asm volatile(
        "mma.sync.aligned.m16n8k16.row.col.f32.bf16.bf16.f32 "
        "{%0,%1,%2,%3}, {%4,%5,%6,%7}, {%8,%9}, {%0,%1,%2,%3};"
        : "+f"(c[0]), "+f"(c[1]), "+f"(c[2]), "+f"(c[3])
        : "r"(a[0]), "r"(a[1]), "r"(a[2]), "r"(a[3]), "r"(b0), "r"(b1));
}

// MODE 0: QKV (BN=256, 8 n-warps, warp tile 64x32); MODE 1: out (BN=128, 4 n-warps, 32x32)
template <int MODE>
__global__ __launch_bounds__(512, 1) void gemm_mma(
    const __nv_bfloat16* __restrict__ Ah, const __nv_bfloat16* __restrict__ Al,
    const __nv_bfloat16* __restrict__ Bh, const __nv_bfloat16* __restrict__ Bl,
    const float* __restrict__ b0v, const float* __restrict__ b1v,
    const float* __restrict__ b2v, float* __restrict__ outp)
{
    constexpr int BN = (MODE == 0) ? 256 : 128;
    constexpr int WN = (MODE == 0) ? 8 : 4;      // warps along N
    constexpr int MF = (MODE == 0) ? 4 : 2;      // 16-row a-frags per warp
    constexpr int ABYTES = 128 * 128;            // 16 KB per A buffer
    constexpr int BBYTES = BN * 128;
    constexpr int OFF_AL = ABYTES;
    constexpr int OFF_BH = 2 * ABYTES;
    constexpr int OFF_BL = 2 * ABYTES + BBYTES;
    constexpr int STAGE = 2 * ABYTES + 2 * BBYTES;
    constexpr int TOTROW8 = (128 + BN) * 8;      // 16B loads per buffer-pair row set

    extern __shared__ __align__(16) uint8_t smem[];
    const uint32_t sbase = smem_u32(smem);

    const int tid = threadIdx.x;
    const int lane = tid & 31;
    const int warp = tid >> 5;
    const int warp_m = warp / WN;
    const int warp_n = warp % WN;

    const int nt = blockIdx.x, mt = blockIdx.y;
    const int m0 = mt * 128;
    const int which = (MODE == 0) ? (nt >> 1) : 0;
    const float* bias = (MODE == 0) ? ((which == 0) ? b0v : (which == 1) ? b1v : b2v) : b0v;
    const int wn0 = (MODE == 0) ? ((nt & 1) * 256) : nt * 128;
    const int bn0 = which * 512 + wn0;

    float C[MF][4][4];
#pragma unroll
    for (int i = 0; i < MF; i++)
#pragma unroll
        for (int j = 0; j < 4; j++)
#pragma unroll
            for (int q = 0; q < 4; q++) C[i][j][q] = 0.f;

    auto fetch = [&](int cc) {
        const uint32_t sb = sbase + (cc & 1) * STAGE;
        const size_t k0b = (size_t)cc * 128;
#pragma unroll
        for (int g = tid; g < TOTROW8; g += 512) {
            int row = g >> 3;
            int c16 = (g & 7) << 4;
            if (row < 128) {
                uint32_t sw = SWZ128((uint32_t)(row * 128 + c16));
                size_t aoff = (size_t)(m0 + row) * 1024 + k0b + c16;
                cpasync16(sb + sw, (const uint8_t*)Ah + aoff);
                cpasync16(sb + OFF_AL + sw, (const uint8_t*)Al + aoff);
            } else {
                int br = row - 128;
                uint32_t sw = SWZ128((uint32_t)(br * 128 + c16));
                size_t boff = (size_t)(bn0 + br) * 1024 + k0b + c16;
                cpasync16(sb + OFF_BH + sw, (const uint8_t*)Bh + boff);
                cpasync16(sb + OFF_BL + sw, (const uint8_t*)Bl + boff);
            }
        }
        asm volatile("cp.async.commit_group;" ::: "memory");
    };

    fetch(0);
    fetch(1);

    for (int cc = 0; cc < 8; cc++) {
        if (cc < 7) asm volatile("cp.async.wait_group 1;" ::: "memory");
        else        asm volatile("cp.async.wait_group 0;" ::: "memory");
        __syncthreads();

        const uint32_t st = sbase + (cc & 1) * STAGE;
        const uint32_t ah_b = st, al_b = st + OFF_AL;
        const uint32_t bh_b = st + OFF_BH, bl_b = st + OFF_BL;

#pragma unroll
        for (int ks = 0; ks < 4; ks++) {
            const int kb = (ks * 16 + (lane >> 4) * 8) * 2;
            const int arow = warp_m * (MF * 16) + (lane & 15);
            const int brow = warp_n * 32 + (lane & 15);

            uint32_t af[MF][4];
#pragma unroll
            for (int mf = 0; mf < MF; mf++)
                ldm_x4(af[mf], ah_b + SWZ128((uint32_t)((arow + mf * 16) * 128 + kb)));
            uint32_t bhf[2][4], blf[2][4];
#pragma unroll
            for (int np = 0; np < 2; np++) {
                ldm_x4(bhf[np], bh_b + SWZ128((uint32_t)((brow + np * 16) * 128 + kb)));
                ldm_x4(blf[np], bl_b + SWZ128((uint32_t)((brow + np * 16) * 128 + kb)));
            }
#pragma unroll
            for (int mf = 0; mf < MF; mf++)
#pragma unroll
                for (int np = 0; np < 2; np++) {
                    mma_16816(C[mf][np * 2 + 0], af[mf], bhf[np][0], bhf[np][2]);
                    mma_16816(C[mf][np * 2 + 1], af[mf], bhf[np][1], bhf[np][3]);
                    mma_16816(C[mf][np * 2 + 0], af[mf], blf[np][0], blf[np][2]);
                    mma_16816(C[mf][np * 2 + 1], af[mf], blf[np][1], blf[np][3]);
                }
#pragma unroll
            for (int mf = 0; mf < MF; mf++)
                ldm_x4(af[mf], al_b + SWZ128((uint32_t)((arow + mf * 16) * 128 + kb)));
#pragma unroll
            for (int mf = 0; mf < MF; mf++)
#pragma unroll
                for (int np = 0; np < 2; np++) {
                    mma_16816(C[mf][np * 2 + 0], af[mf], bhf[np][0], bhf[np][2]);
                    mma_16816(C[mf][np * 2 + 1], af[mf], bhf[np][1], bhf[np][3]);
                }
        }
        __syncthreads();
        if (cc + 2 < 8) fetch(cc + 2);
    }

    // ---- epilogue ----
    const bool dorope = (MODE == 0) && (which < 2) && ((warp_n & 1) == 0);
#pragma unroll
    for (int mf = 0; mf < MF; mf++) {
#pragma unroll
        for (int nf = 0; nf < 4; nf++) {
            int colg = wn0 + warp_n * 32 + nf * 8 + (lane & 3) * 2;
            float bx = bias[colg], by = bias[colg + 1];
            int e = colg & 63;
            float theta = exp2f(-(float)(e >> 1) * 0.83048202372184f);
#pragma unroll
            for (int half = 0; half < 2; half++) {
                int m = m0 + warp_m * (MF * 16) + mf * 16 + (lane >> 2) + half * 8;
                float ox = C[mf][nf][half * 2 + 0] + bx;
                float oy = C[mf][nf][half * 2 + 1] + by;
                if (MODE == 0) {
                    int bb = m >> 11, l = m & 2047;
                    if (dorope) {
                        float sv, cv;
                        sincosf((float)l * theta, &sv, &cv);
                        float nx = cv * ox - sv * oy;
                        float ny = cv * oy + sv * ox;
                        ox = nx; oy = ny;
                    }
                    int hh = colg >> 6;
                    size_t idx = (((size_t)bb * NHEAD + hh) * LSEQ + l) * EDIM + e;
                    if (which == 0) {
                        *(uint32_t*)&g_Qh[idx] = pack_hi2(ox, oy);
                        *(uint32_t*)&g_Ql[idx] = pack_lo2(ox, oy);
                    } else if (which == 1) {
                        *(uint32_t*)&g_Kh[idx] = pack_hi2(ox, oy);
                        *(uint32_t*)&g_Kl[idx] = pack_lo2(ox, oy);
                    } else {
                        float2 o; o.x = ox; o.y = oy;
                        *(float2*)&g_V[idx] = o;
                    }
                } else {
                    float2 o; o.x = ox; o.y = oy;
                    *(float2*)&outp[(size_t)m * DMODEL + colg] = o;
                }
            }
        }
    }
}

#define GSMEM0 (2 * (2 * 128 * 128 + 2 * 256 * 128))   // 196608
#define GSMEM1 (2 * (2 * 128 * 128 + 2 * 128 * 128))   // 131072

// ================= attention: tensor-core S and PV ==========================
#define A_QH 0
#define A_QL 8192
#define A_KH 16384
#define A_KL 24576
#define A_S  32768
#define SSTR 68
#define A_LINV (32768 + 64 * SSTR * 4)
#define ASMEM (A_LINV + 256)

__global__ __launch_bounds__(256) void attn_main(const float* __restrict__ be)
{
    extern __shared__ __align__(16) uint8_t smem[];
    const uint32_t sbase = smem_u32(smem);
    float* Sbuf = (float*)(smem + A_S);
    float* sLinv = (float*)(smem + A_LINV);

    const int bx = blockIdx.x;
    const int tid = threadIdx.x;
    const int lane = tid & 31;
    const int warp = tid >> 5;
    const int warp_m = warp >> 2;   // 0..1: 32-row slab
    const int warp_n = warp & 3;    // 0..3: 16-col slab

    int bb, h, qrow0, krow0, slot;
    bool diag;
    if (bx < 512) {
        int vb = bx & 31; h = (bx >> 5) & 7; bb = bx >> 8;
        qrow0 = vb * 64; krow0 = vb * 64; slot = vb; diag = true;
    } else {
        int y = bx - 512;
        int chunk = y % 31; int t2 = y / 31; h = t2 & 7; bb = t2 >> 3;
        qrow0 = LSEQ - 64; krow0 = chunk * 64; slot = chunk; diag = false;
    }
    const size_t bhbase = ((size_t)bb * NHEAD + h) * LSEQ;
    const size_t qoff = (bhbase + qrow0) * EDIM;
    const size_t koff = (bhbase + krow0) * EDIM;

    {
        const uint4* qh = (const uint4*)(g_Qh + qoff);
        const uint4* ql = (const uint4*)(g_Ql + qoff);
        const uint4* kh = (const uint4*)(g_Kh + koff);
        const uint4* kl = (const uint4*)(g_Kl + koff);
#pragma unroll
        for (int t = 0; t < 2; t++) {
            int g = t * 256 + tid;
            int row = g >> 3, ch = (g & 7) << 4;
            uint32_t sw = SWZ128((uint32_t)(row * 128 + ch));
            *(uint4*)(smem + A_QH + sw) = qh[g];
            *(uint4*)(smem + A_QL + sw) = ql[g];
            *(uint4*)(smem + A_KH + sw) = kh[g];
            *(uint4*)(smem + A_KL + sw) = kl[g];
        }
    }
    __syncthreads();

    // ---- phase 1: S = Q K^T (3-term split), warp tile 32x16 ----
    {
        float Cs[2][2][4];
#pragma unroll
        for (int i = 0; i < 2; i++)
#pragma unroll
            for (int j = 0; j < 2; j++)
#pragma unroll
                for (int q = 0; q < 4; q++) Cs[i][j][q] = 0.f;

#pragma unroll
        for (int ks = 0; ks < 4; ks++) {
            const int kb = (ks * 16 + (lane >> 4) * 8) * 2;
            const int arow = warp_m * 32 + (lane & 15);
            const int brow = warp_n * 16 + (lane & 15);
            uint32_t ah[2][4], bh[4], bl[4];
#pragma unroll
            for (int mf = 0; mf < 2; mf++)
                ldm_x4(ah[mf], sbase + A_QH + SWZ128((uint32_t)((arow + mf * 16) * 128 + kb)));
            ldm_x4(bh, sbase + A_KH + SWZ128((uint32_t)(brow * 128 + kb)));
            ldm_x4(bl, sbase + A_KL + SWZ128((uint32_t)(brow * 128 + kb)));
#pragma unroll
            for (int mf = 0; mf < 2; mf++) {
                mma_16816(Cs[mf][0], ah[mf], bh[0], bh[2]);
                mma_16816(Cs[mf][1], ah[mf], bh[1], bh[3]);
                mma_16816(Cs[mf][0], ah[mf], bl[0], bl[2]);
                mma_16816(Cs[mf][1], ah[mf], bl[1], bl[3]);
            }
#pragma unroll
            for (int mf = 0; mf < 2; mf++)
                ldm_x4(ah[mf], sbase + A_QL + SWZ128((uint32_t)((arow + mf * 16) * 128 + kb)));
#pragma unroll
            for (int mf = 0; mf < 2; mf++) {
                mma_16816(Cs[mf][0], ah[mf], bh[0], bh[2]);
                mma_16816(Cs[mf][1], ah[mf], bh[1], bh[3]);
            }
        }
#pragma unroll
        for (int mf = 0; mf < 2; mf++)
#pragma unroll
            for (int nb = 0; nb < 2; nb++)
#pragma unroll
                for (int half = 0; half < 2; half++) {
                    int r = warp_m * 32 + mf * 16 + (lane >> 2) + half * 8;
                    int c = warp_n * 16 + nb * 8 + (lane & 3) * 2;
                    float2 v;
                    v.x = Cs[mf][nb][half * 2 + 0];
                    v.y = Cs[mf][nb][half * 2 + 1];
                    *(float2*)&Sbuf[r * SSTR + c] = v;
                }
    }
    __syncthreads();

    // ---- softmax + write P hi/lo + stage V^T hi/lo ----
    {
        const int ty = tid >> 4, tx = tid & 15;
        const int r0 = ty << 2, c0 = tx << 2;
        const float biasv = 0.125f * (diag ? be[NHEAD + h] : be[h]);

        float s[4][4], m[4], l[4];
#pragma unroll
        for (int i = 0; i < 4; i++) {
            float4 v4 = *(const float4*)&Sbuf[(r0 + i) * SSTR + c0];
            s[i][0] = v4.x; s[i][1] = v4.y; s[i][2] = v4.z; s[i][3] = v4.w;
        }
#pragma unroll
        for (int i = 0; i < 4; i++) {
            float mm = -1e30f;
#pragma unroll
            for (int j = 0; j < 4; j++) {
                float v = 0.125f * s[i][j] + biasv;
                if (diag && (c0 + j > r0 + i)) v = -1e30f;
                s[i][j] = v;
                mm = fmaxf(mm, v);
            }
            mm = fmaxf(mm, __shfl_xor_sync(0xffffffffu, mm, 1));
            mm = fmaxf(mm, __shfl_xor_sync(0xffffffffu, mm, 2));
            mm = fmaxf(mm, __shfl_xor_sync(0xffffffffu, mm, 4));
            mm = fmaxf(mm, __shfl_xor_sync(0xffffffffu, mm, 8));
            m[i] = mm;
            float ls = 0.f;
#pragma unroll
            for (int j = 0; j < 4; j++) {
                float p = (diag && (c0 + j > r0 + i)) ? 0.f : __expf(s[i][j] - mm);
                s[i][j] = p;
                ls += p;
            }
            ls += __shfl_xor_sync(0xffffffffu, ls, 1);
            ls += __shfl_xor_sync(0xffffffffu, ls, 2);
            ls += __shfl_xor_sync(0xffffffffu, ls, 4);
            ls += __shfl_xor_sync(0xffffffffu, ls, 8);
            l[i] = ls;
        }

#pragma unroll
        for (int i = 0; i < 4; i++) {
            uint2 hp, lp;
            hp.x = pack_hi2(s[i][0], s[i][1]); hp.y = pack_hi2(s[i][2], s[i][3]);
            lp.x = pack_lo2(s[i][0], s[i][1]); lp.y = pack_lo2(s[i][2], s[i][3]);
            uint32_t sw = SWZ128((uint32_t)((r0 + i) * 128 + c0 * 2));
            *(uint2*)(smem + A_QH + sw) = hp;
            *(uint2*)(smem + A_QL + sw) = lp;
        }
        if (tx == 0) {
#pragma unroll
            for (int i = 0; i < 4; i++) {
                if (diag && slot < 31) {
                    sLinv[r0 + i] = 1.f / l[i];
                } else {
                    size_t bh2 = (size_t)bb * NHEAD + h;
                    size_t mb = (((bh2 * 32 + slot) * 64) + r0 + i) * 2;
                    g_ml[mb] = m[i]; g_ml[mb + 1] = l[i];
                }
            }
        }

        const float* Vg = g_V + koff;
        const int c0v = (tid & 15) << 2;
        const int e0v = (tid >> 4) << 2;
        float vv[4][4];
#pragma unroll
        for (int i = 0; i < 4; i++) {
            float4 r4 = *(const float4*)(Vg + (c0v + i) * EDIM + e0v);
            vv[i][0] = r4.x; vv[i][1] = r4.y; vv[i][2] = r4.z; vv[i][3] = r4.w;
        }
#pragma unroll
        for (int j = 0; j < 4; j++) {
            uint2 hp, lp;
            hp.x = pack_hi2(vv[0][j], vv[1][j]); hp.y = pack_hi2(vv[2][j], vv[3][j]);
            lp.x = pack_lo2(vv[0][j], vv[1][j]); lp.y = pack_lo2(vv[2][j], vv[3][j]);
            uint32_t sw = SWZ128((uint32_t)((e0v + j) * 128 + c0v * 2));
            *(uint2*)(smem + A_KH + sw) = hp;
            *(uint2*)(smem + A_KL + sw) = lp;
        }
    }
    __syncthreads();

    // ---- phase 2: O = P V (3-term split) ----
    float Co[2][2][4];
#pragma unroll
    for (int i = 0; i < 2; i++)
#pragma unroll
        for (int j = 0; j < 2; j++)
#pragma unroll
            for (int q = 0; q < 4; q++) Co[i][j][q] = 0.f;

#pragma unroll
    for (int ks = 0; ks < 4; ks++) {
        const int kb = (ks * 16 + (lane >> 4) * 8) * 2;
        const int arow = warp_m * 32 + (lane & 15);
        const int brow = warp_n * 16 + (lane & 15);
        uint32_t ah[2][4], bh[4], bl[4];
#pragma unroll
        for (int mf = 0; mf < 2; mf++)
            ldm_x4(ah[mf], sbase + A_QH + SWZ128((uint32_t)((arow + mf * 16) * 128 + kb)));
        ldm_x4(bh, sbase + A_KH + SWZ128((uint32_t)(brow * 128 + kb)));
        ldm_x4(bl, sbase + A_KL + SWZ128((uint32_t)(brow * 128 + kb)));
#pragma unroll
        for (int mf = 0; mf < 2; mf++) {
            mma_16816(Co[mf][0], ah[mf], bh[0], bh[2]);
            mma_16816(Co[mf][1], ah[mf], bh[1], bh[3]);
            mma_16816(Co[mf][0], ah[mf], bl[0], bl[2]);
            mma_16816(Co[mf][1], ah[mf], bl[1], bl[3]);
        }
#pragma unroll
        for (int mf = 0; mf < 2; mf++)
            ldm_x4(ah[mf], sbase + A_QL + SWZ128((uint32_t)((arow + mf * 16) * 128 + kb)));
#pragma unroll
        for (int mf = 0; mf < 2; mf++) {
            mma_16816(Co[mf][0], ah[mf], bh[0], bh[2]);
            mma_16816(Co[mf][1], ah[mf], bh[1], bh[3]);
        }
    }

#pragma unroll
    for (int mf = 0; mf < 2; mf++)
#pragma unroll
        for (int nb = 0; nb < 2; nb++)
#pragma unroll
            for (int half = 0; half < 2; half++) {
                int r = warp_m * 32 + mf * 16 + (lane >> 2) + half * 8;
                int e = warp_n * 16 + nb * 8 + (lane & 3) * 2;
                float ox = Co[mf][nb][half * 2 + 0];
                float oy = Co[mf][nb][half * 2 + 1];
                if (diag && slot < 31) {
                    float inv = sLinv[r];
                    ox *= inv; oy *= inv;
                    int l2 = qrow0 + r;
                    size_t idx = ((size_t)bb * LSEQ + l2) * DMODEL + h * 64 + e;
                    *(uint32_t*)&g_voh[idx] = pack_hi2(ox, oy);
                    *(uint32_t*)&g_vol[idx] = pack_lo2(ox, oy);
                } else {
                    size_t bh2 = (size_t)bb * NHEAD + h;
                    float2 o; o.x = ox; o.y = oy;
                    *(float2*)&g_part[(((bh2 * 32 + slot) * 64) + r) * 64 + e] = o;
                }
            }
}

// ---------------- attention: merge partials (1024 CTAs, 1 row each) --------
__global__ __launch_bounds__(256) void attn_merge()
{
    __shared__ float sw[32];
    __shared__ float sinvs;
    __shared__ float red[4][64];

    const int bx = blockIdx.x;
    const int bh = bx >> 6;
    const int r  = bx & 63;
    const int tid = threadIdx.x;

    if (tid < 32) {
        int c = tid;
        size_t mb = (((size_t)bh * 32 + c) * 64 + r) * 2;
        float mi = g_ml[mb];
        float li = g_ml[mb + 1];
        float mv = mi;
#pragma unroll
        for (int o = 16; o; o >>= 1) mv = fmaxf(mv, __shfl_xor_sync(0xffffffffu, mv, o));
        float w = __expf(mi - mv);
        float lw = w * li;
#pragma unroll
        for (int o = 16; o; o >>= 1) lw += __shfl_xor_sync(0xffffffffu, lw, o);
        sw[c] = w;
        if (c == 0) sinvs = 1.f / lw;
    }
    __syncthreads();

    const int e = tid & 63, cg = tid >> 6;
    float acc = 0.f;
#pragma unroll
    for (int cq = 0; cq < 8; cq++) {
        int c = cg * 8 + cq;
        acc += sw[c] * g_part[(((size_t)bh * 32 + c) * 64 + r) * 64 + e];
    }
    red[cg][e] = acc;
    __syncthreads();

    if (tid < 64) {
        float s = (red[0][tid] + red[1][tid] + red[2][tid] + red[3][tid]) * sinvs;
        int bb = bh >> 3, h = bh & 7;
        size_t idx = ((size_t)bb * LSEQ + (LSEQ - 64 + r)) * DMODEL + h * 64 + tid;
        __nv_bfloat16 hi = __float2bfloat16(s);
        __nv_bfloat16 lo = __float2bfloat16(s - __bfloat162float(hi));
        g_voh[idx] = hi;
        g_vol[idx] = lo;
    }
}

// ---------------- launch ----------------------------------------------------
extern "C" void kernel_launch(void* const* d_in, const int* in_sizes, int n_in,
                              void* d_out, int out_size)
{
    (void)in_sizes; (void)n_in; (void)out_size;
    const float* x   = (const float*)d_in[0];
    const float* Wq  = (const float*)d_in[1];
    const float* bq  = (const float*)d_in[2];
    const float* Wk  = (const float*)d_in[3];
    const float* bk  = (const float*)d_in[4];
    const float* Wv  = (const float*)d_in[5];
    const float* bv  = (const float*)d_in[6];
    const float* Wo  = (const float*)d_in[7];
    const float* bo  = (const float*)d_in[8];
    const float* be  = (const float*)d_in[9];
    float* out = (float*)d_out;

    cudaFuncSetAttribute(gemm_mma<0>, cudaFuncAttributeMaxDynamicSharedMemorySize, GSMEM0);
    cudaFuncSetAttribute(gemm_mma<1>, cudaFuncAttributeMaxDynamicSharedMemorySize, GSMEM1);
    cudaFuncSetAttribute(attn_main, cudaFuncAttributeMaxDynamicSharedMemorySize, ASMEM);

    __nv_bfloat16 *xh, *xl, *wh, *wl, *voh, *vol, *woh, *wol;
    cudaGetSymbolAddress((void**)&xh, g_xh);
    cudaGetSymbolAddress((void**)&xl, g_xl);
    cudaGetSymbolAddress((void**)&wh, g_wh);
    cudaGetSymbolAddress((void**)&wl, g_wl);
    cudaGetSymbolAddress((void**)&voh, g_voh);
    cudaGetSymbolAddress((void**)&vol, g_vol);
    cudaGetSymbolAddress((void**)&woh, g_woh);
    cudaGetSymbolAddress((void**)&wol, g_wol);

    conv_batch<<<3072, 256>>>(x, Wq, Wk, Wv, Wo);

    dim3 g1(6, 32);                        // N=1536 (3 x 512, BN=256), M=4096
    gemm_mma<0><<<g1, 512, GSMEM0>>>(xh, xl, wh, wl, bq, bk, bv, nullptr);
    attn_main<<<512 + BSZ * NHEAD * 31, 256, ASMEM>>>(be);
    attn_merge<<<1024, 256>>>();
    dim3 g2(4, 32);                        // N=512 (BN=128), M=4096
    gemm_mma<1><<<g2, 512, GSMEM1>>>(voh, vol, woh, wol, bo, nullptr, nullptr, out);
}

// round 16
// speedup vs baseline: 1.1648x; 1.1648x over previous
#include <cuda_runtime.h>
#include <cuda_bf16.h>
#include <math.h>
#include <stdint.h>

// Problem constants (fixed shapes for this benchmark)
#define BSZ 2
#define LSEQ 2048
#define DMODEL 512
#define NHEAD 8
#define EDIM 64
#define NTOK 64
#define NVAR 32

// ---------------- scratch (device globals; no allocation allowed) ----------
__device__ float g_V[BSZ * NHEAD * LSEQ * EDIM];     // fp32 V
__device__ float g_part[BSZ * NHEAD * 32 * 64 * 64]; // partial accumulators
__device__ float g_ml[BSZ * NHEAD * 32 * 64 * 2];    // (m, l) per partial row

// bf16 hi/lo buffers
__device__ __nv_bfloat16 g_xh[4096 * 512], g_xl[4096 * 512];
__device__ __nv_bfloat16 g_wh[3 * 512 * 512], g_wl[3 * 512 * 512];
__device__ __nv_bfloat16 g_Qh[BSZ * NHEAD * LSEQ * EDIM], g_Ql[BSZ * NHEAD * LSEQ * EDIM];
__device__ __nv_bfloat16 g_Kh[BSZ * NHEAD * LSEQ * EDIM], g_Kl[BSZ * NHEAD * LSEQ * EDIM];
__device__ __nv_bfloat16 g_voh[4096 * 512], g_vol[4096 * 512];
__device__ __nv_bfloat16 g_woh[512 * 512], g_wol[512 * 512];

__device__ __forceinline__ uint32_t smem_u32(const void* p) {
    uint32_t a;
    asm("{ .reg .u64 t; cvta.to.shared.u64 t, %1; cvt.u32.u64 %0, t; }"
        : "=r"(a) : "l"(p));
    return a;
}

#define SWZ128(o) ((o) ^ (((o) >> 3) & 0x70))

__device__ __forceinline__ uint32_t pack_hi2(float x, float y) {
    __nv_bfloat16 h0 = __float2bfloat16(x), h1 = __float2bfloat16(y);
    return (uint32_t)__bfloat16_as_ushort(h0) | ((uint32_t)__bfloat16_as_ushort(h1) << 16);
}
__device__ __forceinline__ uint32_t pack_lo2(float x, float y) {
    __nv_bfloat16 h0 = __float2bfloat16(x), h1 = __float2bfloat16(y);
    __nv_bfloat16 l0 = __float2bfloat16(x - __bfloat162float(h0));
    __nv_bfloat16 l1 = __float2bfloat16(y - __bfloat162float(h1));
    return (uint32_t)__bfloat16_as_ushort(l0) | ((uint32_t)__bfloat16_as_ushort(l1) << 16);
}

// ---------------- batched fp32 -> bf16 hi/lo conversion ---------------------
__global__ __launch_bounds__(256) void conv_batch(
    const float* __restrict__ x,
    const float* __restrict__ Wq, const float* __restrict__ Wk,
    const float* __restrict__ Wv, const float* __restrict__ Wo)
{
    int b = blockIdx.x;
    const float* src; __nv_bfloat16 *hi, *lo; int i;
    if (b < 2048) {
        src = x; hi = g_xh; lo = g_xl; i = b * 256 + threadIdx.x;
    } else {
        int seg = (b - 2048) >> 8;
        int sub = (b - 2048) & 255;
        i = sub * 256 + threadIdx.x;
        if (seg == 0)      { src = Wq; hi = g_wh;              lo = g_wl; }
        else if (seg == 1) { src = Wk; hi = g_wh + 262144;     lo = g_wl + 262144; }
        else if (seg == 2) { src = Wv; hi = g_wh + 524288;     lo = g_wl + 524288; }
        else               { src = Wo; hi = g_woh;             lo = g_wol; }
    }
    float4 v = ((const float4*)src)[i];
    uint2 hp, lp;
    hp.x = pack_hi2(v.x, v.y); hp.y = pack_hi2(v.z, v.w);
    lp.x = pack_lo2(v.x, v.y); lp.y = pack_lo2(v.z, v.w);
    ((uint2*)hi)[i] = hp;
    ((uint2*)lo)[i] = lp;
}

// ============ bf16 hi/lo split GEMM: BM=64, 2-stage, 2 CTAs/SM ==============
#define OFF_AL 8192
#define OFF_BH 16384
#define OFF_BL 32768
#define STAGE  49152
#define GSMEM  (2 * STAGE)   // 96 KB -> 2 CTAs/SM

__device__ __forceinline__ void cpasync16(uint32_t dst, const void* src) {
    asm volatile("cp.async.cg.shared.global [%0], [%1], 16;" :: "r"(dst), "l"(src));
}
__device__ __forceinline__ void ldm_x4(uint32_t r[4], uint32_t addr)
{
    asm volatile("ldmatrix.sync.aligned.m8n8.x4.shared.b16 {%0,%1,%2,%3}, [%4];"
                 : "=r"(r[0]), "=r"(r[1]), "=r"(r[2]), "=r"(r[3]) : "r"(addr));
}
__device__ __forceinline__ void mma_16816(
    float c[4], const uint32_t a[4], uint32_t b0, uint32_t b1)
{
    asm volatile(
        "mma.sync.aligned.m16n8k16.row.col.f32.bf16.bf16.f32 "
        "{%0,%1,%2,%3}, {%4,%5,%6,%7}, {%8,%9}, {%0,%1,%2,%3};"
        : "+f"(c[0]), "+f"(c[1]), "+f"(c[2]), "+f"(c[3])
        : "r"(a[0]), "r"(a[1]), "r"(a[2]), "r"(a[3]), "r"(b0), "r"(b1));
}

// MODE 0: QKV scatter (+fused RoPE on Q,K); MODE 1: out projection.
// BM=64, BN=128, 8 warps in 2(m) x 4(n), warp tile 32x32 (MF=2).
template <int MODE>
__global__ __launch_bounds__(256, 2) void gemm_mma(
    const __nv_bfloat16* __restrict__ Ah, const __nv_bfloat16* __restrict__ Al,
    const __nv_bfloat16* __restrict__ Bh, const __nv_bfloat16* __restrict__ Bl,
    const float* __restrict__ b0v, const float* __restrict__ b1v,
    const float* __restrict__ b2v, float* __restrict__ outp)
{
    extern __shared__ __align__(16) uint8_t smem[];
    const uint32_t sbase = smem_u32(smem);

    const int tid = threadIdx.x;
    const int lane = tid & 31;
    const int warp = tid >> 5;
    const int warp_m = warp >> 2;    // 0..1: 32-row slab
    const int warp_n = warp & 3;     // 0..3: 32-col slab

    const int nt = blockIdx.x, mt = blockIdx.y;
    const int m0 = mt * 64;
    const int which = (MODE == 0) ? (nt >> 2) : 0;
    const float* bias = (MODE == 0) ? ((which == 0) ? b0v : (which == 1) ? b1v : b2v) : b0v;
    const int wn0 = (MODE == 0) ? ((nt & 3) * 128) : nt * 128;
    const int bn0 = which * 512 + wn0;

    float C[2][4][4];
#pragma unroll
    for (int i = 0; i < 2; i++)
#pragma unroll
        for (int j = 0; j < 4; j++)
#pragma unroll
            for (int q = 0; q < 4; q++) C[i][j][q] = 0.f;

    auto fetch = [&](int cc) {
        const uint32_t sb = sbase + (cc & 1) * STAGE;
        const size_t k0b = (size_t)cc * 128;
        for (int g = tid; g < 1536; g += 256) {   // (64 + 128) rows x 8
            int row = g >> 3;
            int c16 = (g & 7) << 4;
            if (row < 64) {
                uint32_t sw = SWZ128((uint32_t)(row * 128 + c16));
                size_t aoff = (size_t)(m0 + row) * 1024 + k0b + c16;
                cpasync16(sb + sw, (const uint8_t*)Ah + aoff);
                cpasync16(sb + OFF_AL + sw, (const uint8_t*)Al + aoff);
            } else {
                int br = row - 64;
                uint32_t sw = SWZ128((uint32_t)(br * 128 + c16));
                size_t boff = (size_t)(bn0 + br) * 1024 + k0b + c16;
                cpasync16(sb + OFF_BH + sw, (const uint8_t*)Bh + boff);
                cpasync16(sb + OFF_BL + sw, (const uint8_t*)Bl + boff);
            }
        }
        asm volatile("cp.async.commit_group;" ::: "memory");
    };

    fetch(0);
    fetch(1);

    for (int cc = 0; cc < 8; cc++) {
        if (cc < 7) asm volatile("cp.async.wait_group 1;" ::: "memory");
        else        asm volatile("cp.async.wait_group 0;" ::: "memory");
        __syncthreads();

        const uint32_t st = sbase + (cc & 1) * STAGE;
        const uint32_t ah_b = st, al_b = st + OFF_AL;
        const uint32_t bh_b = st + OFF_BH, bl_b = st + OFF_BL;

#pragma unroll
        for (int ks = 0; ks < 4; ks++) {
            const int kb = (ks * 16 + (lane >> 4) * 8) * 2;
            const int arow = warp_m * 32 + (lane & 15);
            const int brow = warp_n * 32 + (lane & 15);

            uint32_t af[2][4];
#pragma unroll
            for (int mf = 0; mf < 2; mf++)
                ldm_x4(af[mf], ah_b + SWZ128((uint32_t)((arow + mf * 16) * 128 + kb)));
            uint32_t bhf[2][4], blf[2][4];
#pragma unroll
            for (int np = 0; np < 2; np++) {
                ldm_x4(bhf[np], bh_b + SWZ128((uint32_t)((brow + np * 16) * 128 + kb)));
                ldm_x4(blf[np], bl_b + SWZ128((uint32_t)((brow + np * 16) * 128 + kb)));
            }
#pragma unroll
            for (int mf = 0; mf < 2; mf++)
#pragma unroll
                for (int np = 0; np < 2; np++) {
                    mma_16816(C[mf][np * 2 + 0], af[mf], bhf[np][0], bhf[np][2]);
                    mma_16816(C[mf][np * 2 + 1], af[mf], bhf[np][1], bhf[np][3]);
                    mma_16816(C[mf][np * 2 + 0], af[mf], blf[np][0], blf[np][2]);
                    mma_16816(C[mf][np * 2 + 1], af[mf], blf[np][1], blf[np][3]);
                }
#pragma unroll
            for (int mf = 0; mf < 2; mf++)
                ldm_x4(af[mf], al_b + SWZ128((uint32_t)((arow + mf * 16) * 128 + kb)));
#pragma unroll
            for (int mf = 0; mf < 2; mf++)
#pragma unroll
                for (int np = 0; np < 2; np++) {
                    mma_16816(C[mf][np * 2 + 0], af[mf], bhf[np][0], bhf[np][2]);
                    mma_16816(C[mf][np * 2 + 1], af[mf], bhf[np][1], bhf[np][3]);
                }
        }
        __syncthreads();
        if (cc + 2 < 8) fetch(cc + 2);
    }

    // ---- epilogue ----
    const bool dorope = (MODE == 0) && (which < 2) && ((warp_n & 1) == 0);
#pragma unroll
    for (int mf = 0; mf < 2; mf++) {
#pragma unroll
        for (int nf = 0; nf < 4; nf++) {
            int colg = wn0 + warp_n * 32 + nf * 8 + (lane & 3) * 2;
            float bx = bias[colg], by = bias[colg + 1];
            int e = colg & 63;
            float theta = exp2f(-(float)(e >> 1) * 0.83048202372184f);
#pragma unroll
            for (int half = 0; half < 2; half++) {
                int m = m0 + warp_m * 32 + mf * 16 + (lane >> 2) + half * 8;
                float ox = C[mf][nf][half * 2 + 0] + bx;
                float oy = C[mf][nf][half * 2 + 1] + by;
                if (MODE == 0) {
                    int bb = m >> 11, l = m & 2047;
                    if (dorope) {
                        float sv, cv;
                        sincosf((float)l * theta, &sv, &cv);
                        float nx = cv * ox - sv * oy;
                        float ny = cv * oy + sv * ox;
                        ox = nx; oy = ny;
                    }
                    int hh = colg >> 6;
                    size_t idx = (((size_t)bb * NHEAD + hh) * LSEQ + l) * EDIM + e;
                    if (which == 0) {
                        *(uint32_t*)&g_Qh[idx] = pack_hi2(ox, oy);
                        *(uint32_t*)&g_Ql[idx] = pack_lo2(ox, oy);
                    } else if (which == 1) {
                        *(uint32_t*)&g_Kh[idx] = pack_hi2(ox, oy);
                        *(uint32_t*)&g_Kl[idx] = pack_lo2(ox, oy);
                    } else {
                        float2 o; o.x = ox; o.y = oy;
                        *(float2*)&g_V[idx] = o;
                    }
                } else {
                    float2 o; o.x = ox; o.y = oy;
                    *(float2*)&outp[(size_t)m * DMODEL + colg] = o;
                }
            }
        }
    }
}

// ================= attention: tensor-core S and PV ==========================
#define A_QH 0
#define A_QL 8192
#define A_KH 16384
#define A_KL 24576
#define A_S  32768
#define SSTR 68
#define A_LINV (32768 + 64 * SSTR * 4)
#define ASMEM (A_LINV + 256)

__global__ __launch_bounds__(256) void attn_main(const float* __restrict__ be)
{
    extern __shared__ __align__(16) uint8_t smem[];
    const uint32_t sbase = smem_u32(smem);
    float* Sbuf = (float*)(smem + A_S);
    float* sLinv = (float*)(smem + A_LINV);

    const int bx = blockIdx.x;
    const int tid = threadIdx.x;
    const int lane = tid & 31;
    const int warp = tid >> 5;
    const int warp_m = warp >> 2;   // 0..1: 32-row slab
    const int warp_n = warp & 3;    // 0..3: 16-col slab

    int bb, h, qrow0, krow0, slot;
    bool diag;
    if (bx < 512) {
        int vb = bx & 31; h = (bx >> 5) & 7; bb = bx >> 8;
        qrow0 = vb * 64; krow0 = vb * 64; slot = vb; diag = true;
    } else {
        int y = bx - 512;
        int chunk = y % 31; int t2 = y / 31; h = t2 & 7; bb = t2 >> 3;
        qrow0 = LSEQ - 64; krow0 = chunk * 64; slot = chunk; diag = false;
    }
    const size_t bhbase = ((size_t)bb * NHEAD + h) * LSEQ;
    const size_t qoff = (bhbase + qrow0) * EDIM;
    const size_t koff = (bhbase + krow0) * EDIM;

    {
        const uint4* qh = (const uint4*)(g_Qh + qoff);
        const uint4* ql = (const uint4*)(g_Ql + qoff);
        const uint4* kh = (const uint4*)(g_Kh + koff);
        const uint4* kl = (const uint4*)(g_Kl + koff);
#pragma unroll
        for (int t = 0; t < 2; t++) {
            int g = t * 256 + tid;
            int row = g >> 3, ch = (g & 7) << 4;
            uint32_t sw = SWZ128((uint32_t)(row * 128 + ch));
            *(uint4*)(smem + A_QH + sw) = qh[g];
            *(uint4*)(smem + A_QL + sw) = ql[g];
            *(uint4*)(smem + A_KH + sw) = kh[g];
            *(uint4*)(smem + A_KL + sw) = kl[g];
        }
    }
    __syncthreads();

    // ---- phase 1: S = Q K^T (3-term split), warp tile 32x16 ----
    {
        float Cs[2][2][4];
#pragma unroll
        for (int i = 0; i < 2; i++)
#pragma unroll
            for (int j = 0; j < 2; j++)
#pragma unroll
                for (int q = 0; q < 4; q++) Cs[i][j][q] = 0.f;

#pragma unroll
        for (int ks = 0; ks < 4; ks++) {
            const int kb = (ks * 16 + (lane >> 4) * 8) * 2;
            const int arow = warp_m * 32 + (lane & 15);
            const int brow = warp_n * 16 + (lane & 15);
            uint32_t ah[2][4], bh[4], bl[4];
#pragma unroll
            for (int mf = 0; mf < 2; mf++)
                ldm_x4(ah[mf], sbase + A_QH + SWZ128((uint32_t)((arow + mf * 16) * 128 + kb)));
            ldm_x4(bh, sbase + A_KH + SWZ128((uint32_t)(brow * 128 + kb)));
            ldm_x4(bl, sbase + A_KL + SWZ128((uint32_t)(brow * 128 + kb)));
#pragma unroll
            for (int mf = 0; mf < 2; mf++) {
                mma_16816(Cs[mf][0], ah[mf], bh[0], bh[2]);
                mma_16816(Cs[mf][1], ah[mf], bh[1], bh[3]);
                mma_16816(Cs[mf][0], ah[mf], bl[0], bl[2]);
                mma_16816(Cs[mf][1], ah[mf], bl[1], bl[3]);
            }
#pragma unroll
            for (int mf = 0; mf < 2; mf++)
                ldm_x4(ah[mf], sbase + A_QL + SWZ128((uint32_t)((arow + mf * 16) * 128 + kb)));
#pragma unroll
            for (int mf = 0; mf < 2; mf++) {
                mma_16816(Cs[mf][0], ah[mf], bh[0], bh[2]);
                mma_16816(Cs[mf][1], ah[mf], bh[1], bh[3]);
            }
        }
#pragma unroll
        for (int mf = 0; mf < 2; mf++)
#pragma unroll
            for (int nb = 0; nb < 2; nb++)
#pragma unroll
                for (int half = 0; half < 2; half++) {
                    int r = warp_m * 32 + mf * 16 + (lane >> 2) + half * 8;
                    int c = warp_n * 16 + nb * 8 + (lane & 3) * 2;
                    float2 v;
                    v.x = Cs[mf][nb][half * 2 + 0];
                    v.y = Cs[mf][nb][half * 2 + 1];
                    *(float2*)&Sbuf[r * SSTR + c] = v;
                }
    }
    __syncthreads();

    // ---- softmax + write P hi/lo + stage V^T hi/lo ----
    {
        const int ty = tid >> 4, tx = tid & 15;
        const int r0 = ty << 2, c0 = tx << 2;
        const float biasv = 0.125f * (diag ? be[NHEAD + h] : be[h]);

        float s[4][4], m[4], l[4];
#pragma unroll
        for (int i = 0; i < 4; i++) {
            float4 v4 = *(const float4*)&Sbuf[(r0 + i) * SSTR + c0];
            s[i][0] = v4.x; s[i][1] = v4.y; s[i][2] = v4.z; s[i][3] = v4.w;
        }
#pragma unroll
        for (int i = 0; i < 4; i++) {
            float mm = -1e30f;
#pragma unroll
            for (int j = 0; j < 4; j++) {
                float v = 0.125f * s[i][j] + biasv;
                if (diag && (c0 + j > r0 + i)) v = -1e30f;
                s[i][j] = v;
                mm = fmaxf(mm, v);
            }
            mm = fmaxf(mm, __shfl_xor_sync(0xffffffffu, mm, 1));
            mm = fmaxf(mm, __shfl_xor_sync(0xffffffffu, mm, 2));
            mm = fmaxf(mm, __shfl_xor_sync(0xffffffffu, mm, 4));
            mm = fmaxf(mm, __shfl_xor_sync(0xffffffffu, mm, 8));
            m[i] = mm;
            float ls = 0.f;
#pragma unroll
            for (int j = 0; j < 4; j++) {
                float p = (diag && (c0 + j > r0 + i)) ? 0.f : __expf(s[i][j] - mm);
                s[i][j] = p;
                ls += p;
            }
            ls += __shfl_xor_sync(0xffffffffu, ls, 1);
            ls += __shfl_xor_sync(0xffffffffu, ls, 2);
            ls += __shfl_xor_sync(0xffffffffu, ls, 4);
            ls += __shfl_xor_sync(0xffffffffu, ls, 8);
            l[i] = ls;
        }

#pragma unroll
        for (int i = 0; i < 4; i++) {
            uint2 hp, lp;
            hp.x = pack_hi2(s[i][0], s[i][1]); hp.y = pack_hi2(s[i][2], s[i][3]);
            lp.x = pack_lo2(s[i][0], s[i][1]); lp.y = pack_lo2(s[i][2], s[i][3]);
            uint32_t sw = SWZ128((uint32_t)((r0 + i) * 128 + c0 * 2));
            *(uint2*)(smem + A_QH + sw) = hp;
            *(uint2*)(smem + A_QL + sw) = lp;
        }
        if (tx == 0) {
#pragma unroll
            for (int i = 0; i < 4; i++) {
                if (diag && slot < 31) {
                    sLinv[r0 + i] = 1.f / l[i];
                } else {
                    size_t bh2 = (size_t)bb * NHEAD + h;
                    size_t mb = (((bh2 * 32 + slot) * 64) + r0 + i) * 2;
                    g_ml[mb] = m[i]; g_ml[mb + 1] = l[i];
                }
            }
        }

        const float* Vg = g_V + koff;
        const int c0v = (tid & 15) << 2;
        const int e0v = (tid >> 4) << 2;
        float vv[4][4];
#pragma unroll
        for (int i = 0; i < 4; i++) {
            float4 r4 = *(const float4*)(Vg + (c0v + i) * EDIM + e0v);
            vv[i][0] = r4.x; vv[i][1] = r4.y; vv[i][2] = r4.z; vv[i][3] = r4.w;
        }
#pragma unroll
        for (int j = 0; j < 4; j++) {
            uint2 hp, lp;
            hp.x = pack_hi2(vv[0][j], vv[1][j]); hp.y = pack_hi2(vv[2][j], vv[3][j]);
            lp.x = pack_lo2(vv[0][j], vv[1][j]); lp.y = pack_lo2(vv[2][j], vv[3][j]);
            uint32_t sw = SWZ128((uint32_t)((e0v + j) * 128 + c0v * 2));
            *(uint2*)(smem + A_KH + sw) = hp;
            *(uint2*)(smem + A_KL + sw) = lp;
        }
    }
    __syncthreads();

    // ---- phase 2: O = P V (3-term split) ----
    float Co[2][2][4];
#pragma unroll
    for (int i = 0; i < 2; i++)
#pragma unroll
        for (int j = 0; j < 2; j++)
#pragma unroll
            for (int q = 0; q < 4; q++) Co[i][j][q] = 0.f;

#pragma unroll
    for (int ks = 0; ks < 4; ks++) {
        const int kb = (ks * 16 + (lane >> 4) * 8) * 2;
        const int arow = warp_m * 32 + (lane & 15);
        const int brow = warp_n * 16 + (lane & 15);
        uint32_t ah[2][4], bh[4], bl[4];
#pragma unroll
        for (int mf = 0; mf < 2; mf++)
            ldm_x4(ah[mf], sbase + A_QH + SWZ128((uint32_t)((arow + mf * 16) * 128 + kb)));
        ldm_x4(bh, sbase + A_KH + SWZ128((uint32_t)(brow * 128 + kb)));
        ldm_x4(bl, sbase + A_KL + SWZ128((uint32_t)(brow * 128 + kb)));
#pragma unroll
        for (int mf = 0; mf < 2; mf++) {
            mma_16816(Co[mf][0], ah[mf], bh[0], bh[2]);
            mma_16816(Co[mf][1], ah[mf], bh[1], bh[3]);
            mma_16816(Co[mf][0], ah[mf], bl[0], bl[2]);
            mma_16816(Co[mf][1], ah[mf], bl[1], bl[3]);
        }
#pragma unroll
        for (int mf = 0; mf < 2; mf++)
            ldm_x4(ah[mf], sbase + A_QL + SWZ128((uint32_t)((arow + mf * 16) * 128 + kb)));
#pragma unroll
        for (int mf = 0; mf < 2; mf++) {
            mma_16816(Co[mf][0], ah[mf], bh[0], bh[2]);
            mma_16816(Co[mf][1], ah[mf], bh[1], bh[3]);
        }
    }

#pragma unroll
    for (int mf = 0; mf < 2; mf++)
#pragma unroll
        for (int nb = 0; nb < 2; nb++)
#pragma unroll
            for (int half = 0; half < 2; half++) {
                int r = warp_m * 32 + mf * 16 + (lane >> 2) + half * 8;
                int e = warp_n * 16 + nb * 8 + (lane & 3) * 2;
                float ox = Co[mf][nb][half * 2 + 0];
                float oy = Co[mf][nb][half * 2 + 1];
                if (diag && slot < 31) {
                    float inv = sLinv[r];
                    ox *= inv; oy *= inv;
                    int l2 = qrow0 + r;
                    size_t idx = ((size_t)bb * LSEQ + l2) * DMODEL + h * 64 + e;
                    *(uint32_t*)&g_voh[idx] = pack_hi2(ox, oy);
                    *(uint32_t*)&g_vol[idx] = pack_lo2(ox, oy);
                } else {
                    size_t bh2 = (size_t)bb * NHEAD + h;
                    float2 o; o.x = ox; o.y = oy;
                    *(float2*)&g_part[(((bh2 * 32 + slot) * 64) + r) * 64 + e] = o;
                }
            }
}

// ---------------- attention: merge partials (512 CTAs, 2 rows each) --------
__global__ __launch_bounds__(256) void attn_merge()
{
    __shared__ float sw[2][32];
    __shared__ float sinvs[2];
    __shared__ float red[8][2][64];

    const int bx = blockIdx.x;      // 0..511
    const int bh = bx >> 5;
    const int r0 = (bx & 31) << 1;  // 2 rows
    const int tid = threadIdx.x;
    const int lane = tid & 31;

    if (tid < 64) {
        int i = tid >> 5;           // row select (one warp per row)
        int c = lane;
        size_t mb = (((size_t)bh * 32 + c) * 64 + r0 + i) * 2;
        float mi = g_ml[mb];
        float li = g_ml[mb + 1];
        float mv = mi;
#pragma unroll
        for (int o = 16; o; o >>= 1) mv = fmaxf(mv, __shfl_xor_sync(0xffffffffu, mv, o));
        float w = __expf(mi - mv);
        float lw = w * li;
#pragma unroll
        for (int o = 16; o; o >>= 1) lw += __shfl_xor_sync(0xffffffffu, lw, o);
        sw[i][c] = w;
        if (c == 0) sinvs[i] = 1.f / lw;
    }
    __syncthreads();

    const int cg = tid >> 5;        // 0..7 column groups (4 c's each)
    const int e2 = lane << 1;       // float2 position
    float2 acc[2];
    acc[0].x = acc[0].y = acc[1].x = acc[1].y = 0.f;
#pragma unroll
    for (int cq = 0; cq < 4; cq++) {
        int c = cg * 4 + cq;
#pragma unroll
        for (int i = 0; i < 2; i++) {
            float2 p = *(const float2*)&g_part[(((size_t)bh * 32 + c) * 64 + r0 + i) * 64 + e2];
            float w = sw[i][c];
            acc[i].x += w * p.x; acc[i].y += w * p.y;
        }
    }
#pragma unroll
    for (int i = 0; i < 2; i++) {
        red[cg][i][e2] = acc[i].x;
        red[cg][i][e2 + 1] = acc[i].y;
    }
    __syncthreads();

    if (tid < 128) {
        int i = tid >> 6, e = tid & 63;
        float s = 0.f;
#pragma unroll
        for (int g = 0; g < 8; g++) s += red[g][i][e];
        s *= sinvs[i];
        int bb = bh >> 3, h = bh & 7;
        size_t idx = ((size_t)bb * LSEQ + (LSEQ - 64 + r0 + i)) * DMODEL + h * 64 + e;
        __nv_bfloat16 hi = __float2bfloat16(s);
        __nv_bfloat16 lo = __float2bfloat16(s - __bfloat162float(hi));
        g_voh[idx] = hi;
        g_vol[idx] = lo;
    }
}

// ---------------- launch ----------------------------------------------------
extern "C" void kernel_launch(void* const* d_in, const int* in_sizes, int n_in,
                              void* d_out, int out_size)
{
    (void)in_sizes; (void)n_in; (void)out_size;
    const float* x   = (const float*)d_in[0];
    const float* Wq  = (const float*)d_in[1];
    const float* bq  = (const float*)d_in[2];
    const float* Wk  = (const float*)d_in[3];
    const float* bk  = (const float*)d_in[4];
    const float* Wv  = (const float*)d_in[5];
    const float* bv  = (const float*)d_in[6];
    const float* Wo  = (const float*)d_in[7];
    const float* bo  = (const float*)d_in[8];
    const float* be  = (const float*)d_in[9];
    float* out = (float*)d_out;

    cudaFuncSetAttribute(gemm_mma<0>, cudaFuncAttributeMaxDynamicSharedMemorySize, GSMEM);
    cudaFuncSetAttribute(gemm_mma<1>, cudaFuncAttributeMaxDynamicSharedMemorySize, GSMEM);
    cudaFuncSetAttribute(attn_main, cudaFuncAttributeMaxDynamicSharedMemorySize, ASMEM);

    __nv_bfloat16 *xh, *xl, *wh, *wl, *voh, *vol, *woh, *wol;
    cudaGetSymbolAddress((void**)&xh, g_xh);
    cudaGetSymbolAddress((void**)&xl, g_xl);
    cudaGetSymbolAddress((void**)&wh, g_wh);
    cudaGetSymbolAddress((void**)&wl, g_wl);
    cudaGetSymbolAddress((void**)&voh, g_voh);
    cudaGetSymbolAddress((void**)&vol, g_vol);
    cudaGetSymbolAddress((void**)&woh, g_woh);
    cudaGetSymbolAddress((void**)&wol, g_wol);

    conv_batch<<<3072, 256>>>(x, Wq, Wk, Wv, Wo);

    dim3 g1(12, 64);                       // N=1536 (3 x 512, BN=128), M=4096, BM=64
    gemm_mma<0><<<g1, 256, GSMEM>>>(xh, xl, wh, wl, bq, bk, bv, nullptr);
    attn_main<<<512 + BSZ * NHEAD * 31, 256, ASMEM>>>(be);
    attn_merge<<<512, 256>>>();
    dim3 g2(4, 64);                        // N=512 (BN=128), M=4096, BM=64
    gemm_mma<1><<<g2, 256, GSMEM>>>(voh, vol, woh, wol, bo, nullptr, nullptr, out);
}

// round 17
// speedup vs baseline: 1.1989x; 1.0293x over previous
#include <cuda_runtime.h>
#include <cuda_bf16.h>
#include <math.h>
#include <stdint.h>

// Problem constants (fixed shapes for this benchmark)
#define BSZ 2
#define LSEQ 2048
#define DMODEL 512
#define NHEAD 8
#define EDIM 64
#define NTOK 64
#define NVAR 32

// ---------------- scratch (device globals; no allocation allowed) ----------
__device__ float g_part[BSZ * NHEAD * 64 * 32 * 64]; // partials [bh][r][c][e]
__device__ float g_ml[BSZ * NHEAD * 32 * 64 * 2];    // (m, l) per partial row

// bf16 hi/lo buffers
__device__ __nv_bfloat16 g_xh[4096 * 512], g_xl[4096 * 512];
__device__ __nv_bfloat16 g_wh[3 * 512 * 512], g_wl[3 * 512 * 512];
__device__ __nv_bfloat16 g_Qh[BSZ * NHEAD * LSEQ * EDIM], g_Ql[BSZ * NHEAD * LSEQ * EDIM];
__device__ __nv_bfloat16 g_Kh[BSZ * NHEAD * LSEQ * EDIM], g_Kl[BSZ * NHEAD * LSEQ * EDIM];
__device__ __nv_bfloat16 g_Vh[BSZ * NHEAD * LSEQ * EDIM], g_Vl[BSZ * NHEAD * LSEQ * EDIM];
__device__ __nv_bfloat16 g_voh[4096 * 512], g_vol[4096 * 512];
__device__ __nv_bfloat16 g_woh[512 * 512], g_wol[512 * 512];

__device__ __forceinline__ uint32_t smem_u32(const void* p) {
    uint32_t a;
    asm("{ .reg .u64 t; cvta.to.shared.u64 t, %1; cvt.u32.u64 %0, t; }"
        : "=r"(a) : "l"(p));
    return a;
}

#define SWZ128(o) ((o) ^ (((o) >> 3) & 0x70))

__device__ __forceinline__ uint32_t pack_hi2(float x, float y) {
    __nv_bfloat16 h0 = __float2bfloat16(x), h1 = __float2bfloat16(y);
    return (uint32_t)__bfloat16_as_ushort(h0) | ((uint32_t)__bfloat16_as_ushort(h1) << 16);
}
__device__ __forceinline__ uint32_t pack_lo2(float x, float y) {
    __nv_bfloat16 h0 = __float2bfloat16(x), h1 = __float2bfloat16(y);
    __nv_bfloat16 l0 = __float2bfloat16(x - __bfloat162float(h0));
    __nv_bfloat16 l1 = __float2bfloat16(y - __bfloat162float(h1));
    return (uint32_t)__bfloat16_as_ushort(l0) | ((uint32_t)__bfloat16_as_ushort(l1) << 16);
}

// ---------------- batched fp32 -> bf16 hi/lo conversion ---------------------
__global__ __launch_bounds__(256) void conv_batch(
    const float* __restrict__ x,
    const float* __restrict__ Wq, const float* __restrict__ Wk,
    const float* __restrict__ Wv, const float* __restrict__ Wo)
{
    int b = blockIdx.x;
    const float* src; __nv_bfloat16 *hi, *lo; int i;
    if (b < 2048) {
        src = x; hi = g_xh; lo = g_xl; i = b * 256 + threadIdx.x;
    } else {
        int seg = (b - 2048) >> 8;
        int sub = (b - 2048) & 255;
        i = sub * 256 + threadIdx.x;
        if (seg == 0)      { src = Wq; hi = g_wh;              lo = g_wl; }
        else if (seg == 1) { src = Wk; hi = g_wh + 262144;     lo = g_wl + 262144; }
        else if (seg == 2) { src = Wv; hi = g_wh + 524288;     lo = g_wl + 524288; }
        else               { src = Wo; hi = g_woh;             lo = g_wol; }
    }
    float4 v = ((const float4*)src)[i];
    uint2 hp, lp;
    hp.x = pack_hi2(v.x, v.y); hp.y = pack_hi2(v.z, v.w);
    lp.x = pack_lo2(v.x, v.y); lp.y = pack_lo2(v.z, v.w);
    ((uint2*)hi)[i] = hp;
    ((uint2*)lo)[i] = lp;
}

// ============ bf16 hi/lo split GEMM: BM=64, 2-stage, 2 CTAs/SM ==============
#define OFF_AL 8192
#define OFF_BH 16384
#define OFF_BL 32768
#define STAGE  49152
#define GSMEM  (2 * STAGE)   // 96 KB -> 2 CTAs/SM

__device__ __forceinline__ void cpasync16(uint32_t dst, const void* src) {
    asm volatile("cp.async.cg.shared.global [%0], [%1], 16;" :: "r"(dst), "l"(src));
}
__device__ __forceinline__ void ldm_x4(uint32_t r[4], uint32_t addr)
{
    asm volatile("ldmatrix.sync.aligned.m8n8.x4.shared.b16 {%0,%1,%2,%3}, [%4];"
                 : "=r"(r[0]), "=r"(r[1]), "=r"(r[2]), "=r"(r[3]) : "r"(addr));
}
__device__ __forceinline__ void ldm_x4_trans(uint32_t r[4], uint32_t addr)
{
    asm volatile("ldmatrix.sync.aligned.m8n8.x4.trans.shared.b16 {%0,%1,%2,%3}, [%4];"
                 : "=r"(r[0]), "=r"(r[1]), "=r"(r[2]), "=r"(r[3]) : "r"(addr));
}
__device__ __forceinline__ void mma_16816(
    float c[4], const uint32_t a[4], uint32_t b0, uint32_t b1)
{
    asm volatile(
        "mma.sync.aligned.m16n8k16.row.col.f32.bf16.bf16.f32 "
        "{%0,%1,%2,%3}, {%4,%5,%6,%7}, {%8,%9}, {%0,%1,%2,%3};"
        : "+f"(c[0]), "+f"(c[1]), "+f"(c[2]), "+f"(c[3])
        : "r"(a[0]), "r"(a[1]), "r"(a[2]), "r"(a[3]), "r"(b0), "r"(b1));
}

// MODE 0: QKV scatter (+fused RoPE on Q,K); MODE 1: out projection.
// BM=64, BN=128, 8 warps in 2(m) x 4(n), warp tile 32x32 (MF=2).
template <int MODE>
__global__ __launch_bounds__(256, 2) void gemm_mma(
    const __nv_bfloat16* __restrict__ Ah, const __nv_bfloat16* __restrict__ Al,
    const __nv_bfloat16* __restrict__ Bh, const __nv_bfloat16* __restrict__ Bl,
    const float* __restrict__ b0v, const float* __restrict__ b1v,
    const float* __restrict__ b2v, float* __restrict__ outp)
{
    extern __shared__ __align__(16) uint8_t smem[];
    const uint32_t sbase = smem_u32(smem);

    const int tid = threadIdx.x;
    const int lane = tid & 31;
    const int warp = tid >> 5;
    const int warp_m = warp >> 2;    // 0..1: 32-row slab
    const int warp_n = warp & 3;     // 0..3: 32-col slab

    const int nt = blockIdx.x, mt = blockIdx.y;
    const int m0 = mt * 64;
    const int which = (MODE == 0) ? (nt >> 2) : 0;
    const float* bias = (MODE == 0) ? ((which == 0) ? b0v : (which == 1) ? b1v : b2v) : b0v;
    const int wn0 = (MODE == 0) ? ((nt & 3) * 128) : nt * 128;
    const int bn0 = which * 512 + wn0;

    float C[2][4][4];
#pragma unroll
    for (int i = 0; i < 2; i++)
#pragma unroll
        for (int j = 0; j < 4; j++)
#pragma unroll
            for (int q = 0; q < 4; q++) C[i][j][q] = 0.f;

    auto fetch = [&](int cc) {
        const uint32_t sb = sbase + (cc & 1) * STAGE;
        const size_t k0b = (size_t)cc * 128;
        for (int g = tid; g < 1536; g += 256) {   // (64 + 128) rows x 8
            int row = g >> 3;
            int c16 = (g & 7) << 4;
            if (row < 64) {
                uint32_t sw = SWZ128((uint32_t)(row * 128 + c16));
                size_t aoff = (size_t)(m0 + row) * 1024 + k0b + c16;
                cpasync16(sb + sw, (const uint8_t*)Ah + aoff);
                cpasync16(sb + OFF_AL + sw, (const uint8_t*)Al + aoff);
            } else {
                int br = row - 64;
                uint32_t sw = SWZ128((uint32_t)(br * 128 + c16));
                size_t boff = (size_t)(bn0 + br) * 1024 + k0b + c16;
                cpasync16(sb + OFF_BH + sw, (const uint8_t*)Bh + boff);
                cpasync16(sb + OFF_BL + sw, (const uint8_t*)Bl + boff);
            }
        }
        asm volatile("cp.async.commit_group;" ::: "memory");
    };

    fetch(0);
    fetch(1);

    for (int cc = 0; cc < 8; cc++) {
        if (cc < 7) asm volatile("cp.async.wait_group 1;" ::: "memory");
        else        asm volatile("cp.async.wait_group 0;" ::: "memory");
        __syncthreads();

        const uint32_t st = sbase + (cc & 1) * STAGE;
        const uint32_t ah_b = st, al_b = st + OFF_AL;
        const uint32_t bh_b = st + OFF_BH, bl_b = st + OFF_BL;

#pragma unroll
        for (int ks = 0; ks < 4; ks++) {
            const int kb = (ks * 16 + (lane >> 4) * 8) * 2;
            const int arow = warp_m * 32 + (lane & 15);
            const int brow = warp_n * 32 + (lane & 15);

            uint32_t af[2][4];
#pragma unroll
            for (int mf = 0; mf < 2; mf++)
                ldm_x4(af[mf], ah_b + SWZ128((uint32_t)((arow + mf * 16) * 128 + kb)));
            uint32_t bhf[2][4], blf[2][4];
#pragma unroll
            for (int np = 0; np < 2; np++) {
                ldm_x4(bhf[np], bh_b + SWZ128((uint32_t)((brow + np * 16) * 128 + kb)));
                ldm_x4(blf[np], bl_b + SWZ128((uint32_t)((brow + np * 16) * 128 + kb)));
            }
#pragma unroll
            for (int mf = 0; mf < 2; mf++)
#pragma unroll
                for (int np = 0; np < 2; np++) {
                    mma_16816(C[mf][np * 2 + 0], af[mf], bhf[np][0], bhf[np][2]);
                    mma_16816(C[mf][np * 2 + 1], af[mf], bhf[np][1], bhf[np][3]);
                    mma_16816(C[mf][np * 2 + 0], af[mf], blf[np][0], blf[np][2]);
                    mma_16816(C[mf][np * 2 + 1], af[mf], blf[np][1], blf[np][3]);
                }
#pragma unroll
            for (int mf = 0; mf < 2; mf++)
                ldm_x4(af[mf], al_b + SWZ128((uint32_t)((arow + mf * 16) * 128 + kb)));
#pragma unroll
            for (int mf = 0; mf < 2; mf++)
#pragma unroll
                for (int np = 0; np < 2; np++) {
                    mma_16816(C[mf][np * 2 + 0], af[mf], bhf[np][0], bhf[np][2]);
                    mma_16816(C[mf][np * 2 + 1], af[mf], bhf[np][1], bhf[np][3]);
                }
        }
        __syncthreads();
        if (cc + 2 < 8) fetch(cc + 2);
    }

    // ---- epilogue ----
    const bool dorope = (MODE == 0) && (which < 2) && ((warp_n & 1) == 0);
#pragma unroll
    for (int mf = 0; mf < 2; mf++) {
#pragma unroll
        for (int nf = 0; nf < 4; nf++) {
            int colg = wn0 + warp_n * 32 + nf * 8 + (lane & 3) * 2;
            float bx = bias[colg], by = bias[colg + 1];
            int e = colg & 63;
            float theta = exp2f(-(float)(e >> 1) * 0.83048202372184f);
#pragma unroll
            for (int half = 0; half < 2; half++) {
                int m = m0 + warp_m * 32 + mf * 16 + (lane >> 2) + half * 8;
                float ox = C[mf][nf][half * 2 + 0] + bx;
                float oy = C[mf][nf][half * 2 + 1] + by;
                if (MODE == 0) {
                    int bb = m >> 11, l = m & 2047;
                    if (dorope) {
                        float sv, cv;
                        sincosf((float)l * theta, &sv, &cv);
                        float nx = cv * ox - sv * oy;
                        float ny = cv * oy + sv * ox;
                        ox = nx; oy = ny;
                    }
                    int hh = colg >> 6;
                    size_t idx = (((size_t)bb * NHEAD + hh) * LSEQ + l) * EDIM + e;
                    if (which == 0) {
                        *(uint32_t*)&g_Qh[idx] = pack_hi2(ox, oy);
                        *(uint32_t*)&g_Ql[idx] = pack_lo2(ox, oy);
                    } else if (which == 1) {
                        *(uint32_t*)&g_Kh[idx] = pack_hi2(ox, oy);
                        *(uint32_t*)&g_Kl[idx] = pack_lo2(ox, oy);
                    } else {
                        *(uint32_t*)&g_Vh[idx] = pack_hi2(ox, oy);
                        *(uint32_t*)&g_Vl[idx] = pack_lo2(ox, oy);
                    }
                } else {
                    float2 o; o.x = ox; o.y = oy;
                    *(float2*)&outp[(size_t)m * DMODEL + colg] = o;
                }
            }
        }
    }
}

// ================= attention: tensor-core S and PV ==========================
#define A_QH 0
#define A_QL 8192
#define A_KH 16384
#define A_KL 24576
#define A_S  32768
#define SSTR 68
#define A_LINV (32768 + 64 * SSTR * 4)
#define ASMEM (A_LINV + 256)

__global__ __launch_bounds__(256) void attn_main(const float* __restrict__ be)
{
    extern __shared__ __align__(16) uint8_t smem[];
    const uint32_t sbase = smem_u32(smem);
    float* Sbuf = (float*)(smem + A_S);
    float* sLinv = (float*)(smem + A_LINV);

    const int bx = blockIdx.x;
    const int tid = threadIdx.x;
    const int lane = tid & 31;
    const int warp = tid >> 5;
    const int warp_m = warp >> 2;   // 0..1: 32-row slab
    const int warp_n = warp & 3;    // 0..3: 16-col slab

    int bb, h, qrow0, krow0, slot;
    bool diag;
    if (bx < 512) {
        int vb = bx & 31; h = (bx >> 5) & 7; bb = bx >> 8;
        qrow0 = vb * 64; krow0 = vb * 64; slot = vb; diag = true;
    } else {
        int y = bx - 512;
        int chunk = y % 31; int t2 = y / 31; h = t2 & 7; bb = t2 >> 3;
        qrow0 = LSEQ - 64; krow0 = chunk * 64; slot = chunk; diag = false;
    }
    const size_t bhbase = ((size_t)bb * NHEAD + h) * LSEQ;
    const size_t qoff = (bhbase + qrow0) * EDIM;
    const size_t koff = (bhbase + krow0) * EDIM;

    {
        const uint4* qh = (const uint4*)(g_Qh + qoff);
        const uint4* ql = (const uint4*)(g_Ql + qoff);
        const uint4* kh = (const uint4*)(g_Kh + koff);
        const uint4* kl = (const uint4*)(g_Kl + koff);
#pragma unroll
        for (int t = 0; t < 2; t++) {
            int g = t * 256 + tid;
            int row = g >> 3, ch = (g & 7) << 4;
            uint32_t sw = SWZ128((uint32_t)(row * 128 + ch));
            *(uint4*)(smem + A_QH + sw) = qh[g];
            *(uint4*)(smem + A_QL + sw) = ql[g];
            *(uint4*)(smem + A_KH + sw) = kh[g];
            *(uint4*)(smem + A_KL + sw) = kl[g];
        }
    }
    __syncthreads();

    // ---- phase 1: S = Q K^T (3-term split), warp tile 32x16 ----
    {
        float Cs[2][2][4];
#pragma unroll
        for (int i = 0; i < 2; i++)
#pragma unroll
            for (int j = 0; j < 2; j++)
#pragma unroll
                for (int q = 0; q < 4; q++) Cs[i][j][q] = 0.f;

#pragma unroll
        for (int ks = 0; ks < 4; ks++) {
            const int kb = (ks * 16 + (lane >> 4) * 8) * 2;
            const int arow = warp_m * 32 + (lane & 15);
            const int brow = warp_n * 16 + (lane & 15);
            uint32_t ah[2][4], bh[4], bl[4];
#pragma unroll
            for (int mf = 0; mf < 2; mf++)
                ldm_x4(ah[mf], sbase + A_QH + SWZ128((uint32_t)((arow + mf * 16) * 128 + kb)));
            ldm_x4(bh, sbase + A_KH + SWZ128((uint32_t)(brow * 128 + kb)));
            ldm_x4(bl, sbase + A_KL + SWZ128((uint32_t)(brow * 128 + kb)));
#pragma unroll
            for (int mf = 0; mf < 2; mf++) {
                mma_16816(Cs[mf][0], ah[mf], bh[0], bh[2]);
                mma_16816(Cs[mf][1], ah[mf], bh[1], bh[3]);
                mma_16816(Cs[mf][0], ah[mf], bl[0], bl[2]);
                mma_16816(Cs[mf][1], ah[mf], bl[1], bl[3]);
            }
#pragma unroll
            for (int mf = 0; mf < 2; mf++)
                ldm_x4(ah[mf], sbase + A_QL + SWZ128((uint32_t)((arow + mf * 16) * 128 + kb)));
#pragma unroll
            for (int mf = 0; mf < 2; mf++) {
                mma_16816(Cs[mf][0], ah[mf], bh[0], bh[2]);
                mma_16816(Cs[mf][1], ah[mf], bh[1], bh[3]);
            }
        }
#pragma unroll
        for (int mf = 0; mf < 2; mf++)
#pragma unroll
            for (int nb = 0; nb < 2; nb++)
#pragma unroll
                for (int half = 0; half < 2; half++) {
                    int r = warp_m * 32 + mf * 16 + (lane >> 2) + half * 8;
                    int c = warp_n * 16 + nb * 8 + (lane & 3) * 2;
                    float2 v;
                    v.x = Cs[mf][nb][half * 2 + 0];
                    v.y = Cs[mf][nb][half * 2 + 1];
                    *(float2*)&Sbuf[r * SSTR + c] = v;
                }
    }
    __syncthreads();

    // ---- softmax + write P hi/lo + stage V hi/lo ([c][e], for trans-ldm) --
    {
        const int ty = tid >> 4, tx = tid & 15;
        const int r0 = ty << 2, c0 = tx << 2;
        const float biasv = 0.125f * (diag ? be[NHEAD + h] : be[h]);

        float s[4][4], m[4], l[4];
#pragma unroll
        for (int i = 0; i < 4; i++) {
            float4 v4 = *(const float4*)&Sbuf[(r0 + i) * SSTR + c0];
            s[i][0] = v4.x; s[i][1] = v4.y; s[i][2] = v4.z; s[i][3] = v4.w;
        }
#pragma unroll
        for (int i = 0; i < 4; i++) {
            float mm = -1e30f;
#pragma unroll
            for (int j = 0; j < 4; j++) {
                float v = 0.125f * s[i][j] + biasv;
                if (diag && (c0 + j > r0 + i)) v = -1e30f;
                s[i][j] = v;
                mm = fmaxf(mm, v);
            }
            mm = fmaxf(mm, __shfl_xor_sync(0xffffffffu, mm, 1));
            mm = fmaxf(mm, __shfl_xor_sync(0xffffffffu, mm, 2));
            mm = fmaxf(mm, __shfl_xor_sync(0xffffffffu, mm, 4));
            mm = fmaxf(mm, __shfl_xor_sync(0xffffffffu, mm, 8));
            m[i] = mm;
            float ls = 0.f;
#pragma unroll
            for (int j = 0; j < 4; j++) {
                float p = (diag && (c0 + j > r0 + i)) ? 0.f : __expf(s[i][j] - mm);
                s[i][j] = p;
                ls += p;
            }
            ls += __shfl_xor_sync(0xffffffffu, ls, 1);
            ls += __shfl_xor_sync(0xffffffffu, ls, 2);
            ls += __shfl_xor_sync(0xffffffffu, ls, 4);
            ls += __shfl_xor_sync(0xffffffffu, ls, 8);
            l[i] = ls;
        }

#pragma unroll
        for (int i = 0; i < 4; i++) {
            uint2 hp, lp;
            hp.x = pack_hi2(s[i][0], s[i][1]); hp.y = pack_hi2(s[i][2], s[i][3]);
            lp.x = pack_lo2(s[i][0], s[i][1]); lp.y = pack_lo2(s[i][2], s[i][3]);
            uint32_t sw = SWZ128((uint32_t)((r0 + i) * 128 + c0 * 2));
            *(uint2*)(smem + A_QH + sw) = hp;
            *(uint2*)(smem + A_QL + sw) = lp;
        }
        if (tx == 0) {
#pragma unroll
            for (int i = 0; i < 4; i++) {
                if (diag && slot < 31) {
                    sLinv[r0 + i] = 1.f / l[i];
                } else {
                    size_t bh2 = (size_t)bb * NHEAD + h;
                    size_t mb = (((bh2 * 32 + slot) * 64) + r0 + i) * 2;
                    g_ml[mb] = m[i]; g_ml[mb + 1] = l[i];
                }
            }
        }

        // stage V hi/lo [c][e] (rows = c, 128B) into A_KH / A_KL
        const uint8_t* vh = (const uint8_t*)(g_Vh + koff);
        const uint8_t* vl = (const uint8_t*)(g_Vl + koff);
#pragma unroll
        for (int t = 0; t < 2; t++) {
            int g = t * 256 + tid;
            int row = g >> 3, ch = (g & 7) << 4;
            uint32_t sw = SWZ128((uint32_t)(row * 128 + ch));
            *(uint4*)(smem + A_KH + sw) = *(const uint4*)(vh + row * 128 + ch);
            *(uint4*)(smem + A_KL + sw) = *(const uint4*)(vl + row * 128 + ch);
        }
    }
    __syncthreads();

    // ---- phase 2: O = P V (3-term split, B-frags via trans-ldmatrix) ------
    float Co[2][2][4];
#pragma unroll
    for (int i = 0; i < 2; i++)
#pragma unroll
        for (int j = 0; j < 2; j++)
#pragma unroll
            for (int q = 0; q < 4; q++) Co[i][j][q] = 0.f;

#pragma unroll
    for (int ks = 0; ks < 4; ks++) {
        const int kb = (ks * 16 + (lane >> 4) * 8) * 2;
        const int arow = warp_m * 32 + (lane & 15);
        // trans addressing: lanes 0-7 tile (k0-7,n0-7), 8-15 (k8-15,n0-7),
        // 16-23 (k0-7,n8-15), 24-31 (k8-15,n8-15); rows = c (k)
        const int krow_t = ks * 16 + ((lane >> 3) & 1) * 8 + (lane & 7);
        const int ecol = (warp_n * 16 + (lane >> 4) * 8) * 2;
        const uint32_t vaddr = SWZ128((uint32_t)(krow_t * 128 + ecol));

        uint32_t ah[2][4], vbh[4], vbl[4];
#pragma unroll
        for (int mf = 0; mf < 2; mf++)
            ldm_x4(ah[mf], sbase + A_QH + SWZ128((uint32_t)((arow + mf * 16) * 128 + kb)));
        ldm_x4_trans(vbh, sbase + A_KH + vaddr);
        ldm_x4_trans(vbl, sbase + A_KL + vaddr);
        // n-block0: (b0,b1) = (r0,r1); n-block1: (r2,r3)
#pragma unroll
        for (int mf = 0; mf < 2; mf++) {
            mma_16816(Co[mf][0], ah[mf], vbh[0], vbh[1]);
            mma_16816(Co[mf][1], ah[mf], vbh[2], vbh[3]);
            mma_16816(Co[mf][0], ah[mf], vbl[0], vbl[1]);
            mma_16816(Co[mf][1], ah[mf], vbl[2], vbl[3]);
        }
#pragma unroll
        for (int mf = 0; mf < 2; mf++)
            ldm_x4(ah[mf], sbase + A_QL + SWZ128((uint32_t)((arow + mf * 16) * 128 + kb)));
#pragma unroll
        for (int mf = 0; mf < 2; mf++) {
            mma_16816(Co[mf][0], ah[mf], vbh[0], vbh[1]);
            mma_16816(Co[mf][1], ah[mf], vbh[2], vbh[3]);
        }
    }

#pragma unroll
    for (int mf = 0; mf < 2; mf++)
#pragma unroll
        for (int nb = 0; nb < 2; nb++)
#pragma unroll
            for (int half = 0; half < 2; half++) {
                int r = warp_m * 32 + mf * 16 + (lane >> 2) + half * 8;
                int e = warp_n * 16 + nb * 8 + (lane & 3) * 2;
                float ox = Co[mf][nb][half * 2 + 0];
                float oy = Co[mf][nb][half * 2 + 1];
                if (diag && slot < 31) {
                    float inv = sLinv[r];
                    ox *= inv; oy *= inv;
                    int l2 = qrow0 + r;
                    size_t idx = ((size_t)bb * LSEQ + l2) * DMODEL + h * 64 + e;
                    *(uint32_t*)&g_voh[idx] = pack_hi2(ox, oy);
                    *(uint32_t*)&g_vol[idx] = pack_lo2(ox, oy);
                } else {
                    size_t bh2 = (size_t)bb * NHEAD + h;
                    float2 o; o.x = ox; o.y = oy;
                    // partials [bh][r][c][e]
                    *(float2*)&g_part[(((bh2 * 64 + r) * 32) + slot) * 64 + e] = o;
                }
            }
}

// -------- attention: merge partials (1024 CTAs, 1 row, contiguous 8KB) -----
__global__ __launch_bounds__(256) void attn_merge()
{
    __shared__ float sw[32];
    __shared__ float sinvs;
    __shared__ float red[8][64];

    const int bx = blockIdx.x;      // 0..1023
    const int bh = bx >> 6;
    const int r  = bx & 63;
    const int tid = threadIdx.x;
    const int lane = tid & 31;

    if (tid < 32) {
        int c = lane;
        size_t mb = (((size_t)bh * 32 + c) * 64 + r) * 2;
        float mi = g_ml[mb];
        float li = g_ml[mb + 1];
        float mv = mi;
#pragma unroll
        for (int o = 16; o; o >>= 1) mv = fmaxf(mv, __shfl_xor_sync(0xffffffffu, mv, o));
        float w = __expf(mi - mv);
        float lw = w * li;
#pragma unroll
        for (int o = 16; o; o >>= 1) lw += __shfl_xor_sync(0xffffffffu, lw, o);
        sw[c] = w;
        if (c == 0) sinvs = 1.f / lw;
    }
    __syncthreads();

    // [bh][r][c][e]: row base is one contiguous 8KB block
    const float* pbase = &g_part[((size_t)bh * 64 + r) * 32 * 64];
    const int cg = tid >> 5;        // 0..7 groups of 4 c's
    const int e2 = lane << 1;
    float2 acc; acc.x = acc.y = 0.f;
#pragma unroll
    for (int cq = 0; cq < 4; cq++) {
        int c = cg * 4 + cq;
        float2 p = *(const float2*)&pbase[c * 64 + e2];
        float w = sw[c];
        acc.x += w * p.x; acc.y += w * p.y;
    }
    red[cg][e2] = acc.x;
    red[cg][e2 + 1] = acc.y;
    __syncthreads();

    if (tid < 64) {
        float s = 0.f;
#pragma unroll
        for (int g = 0; g < 8; g++) s += red[g][tid];
        s *= sinvs;
        int bb = bh >> 3, h = bh & 7;
        size_t idx = ((size_t)bb * LSEQ + (LSEQ - 64 + r)) * DMODEL + h * 64 + tid;
        __nv_bfloat16 hi = __float2bfloat16(s);
        __nv_bfloat16 lo = __float2bfloat16(s - __bfloat162float(hi));
        g_voh[idx] = hi;
        g_vol[idx] = lo;
    }
}

// ---------------- launch ----------------------------------------------------
extern "C" void kernel_launch(void* const* d_in, const int* in_sizes, int n_in,
                              void* d_out, int out_size)
{
    (void)in_sizes; (void)n_in; (void)out_size;
    const float* x   = (const float*)d_in[0];
    const float* Wq  = (const float*)d_in[1];
    const float* bq  = (const float*)d_in[2];
    const float* Wk  = (const float*)d_in[3];
    const float* bk  = (const float*)d_in[4];
    const float* Wv  = (const float*)d_in[5];
    const float* bv  = (const float*)d_in[6];
    const float* Wo  = (const float*)d_in[7];
    const float* bo  = (const float*)d_in[8];
    const float* be  = (const float*)d_in[9];
    float* out = (float*)d_out;

    cudaFuncSetAttribute(gemm_mma<0>, cudaFuncAttributeMaxDynamicSharedMemorySize, GSMEM);
    cudaFuncSetAttribute(gemm_mma<1>, cudaFuncAttributeMaxDynamicSharedMemorySize, GSMEM);
    cudaFuncSetAttribute(attn_main, cudaFuncAttributeMaxDynamicSharedMemorySize, ASMEM);

    __nv_bfloat16 *xh, *xl, *wh, *wl, *voh, *vol, *woh, *wol;
    cudaGetSymbolAddress((void**)&xh, g_xh);
    cudaGetSymbolAddress((void**)&xl, g_xl);
    cudaGetSymbolAddress((void**)&wh, g_wh);
    cudaGetSymbolAddress((void**)&wl, g_wl);
    cudaGetSymbolAddress((void**)&voh, g_voh);
    cudaGetSymbolAddress((void**)&vol, g_vol);
    cudaGetSymbolAddress((void**)&woh, g_woh);
    cudaGetSymbolAddress((void**)&wol, g_wol);

    conv_batch<<<3072, 256>>>(x, Wq, Wk, Wv, Wo);

    dim3 g1(12, 64);                       // N=1536 (3 x 512, BN=128), M=4096, BM=64
    gemm_mma<0><<<g1, 256, GSMEM>>>(xh, xl, wh, wl, bq, bk, bv, nullptr);
    attn_main<<<512 + BSZ * NHEAD * 31, 256, ASMEM>>>(be);
    attn_merge<<<1024, 256>>>();
    dim3 g2(4, 64);                        // N=512 (BN=128), M=4096, BM=64
    gemm_mma<1><<<g2, 256, GSMEM>>>(voh, vol, woh, wol, bo, nullptr, nullptr, out);
}